// round 1
// baseline (speedup 1.0000x reference)
#include <cuda_runtime.h>
#include <math.h>

#define NO 2048
#define NI 16
#define NF 4
#define ND 128
#define NN 8
#define ND2 64

// SMEM layout (float offsets)
#define OFF_FAC   0        // 16*4*128 = 8192
#define OFF_FEAT  8192     // 16*128   = 2048
#define OFF_W1    10240    // 128*128  = 16384
#define OFF_W2    26624    // 128*128  = 16384
#define OFF_H     43008    // 96*128   = 12288
#define OFF_ADD   55296    // 4*128    = 512
#define OFF_B1    55808    // 128
#define OFF_B2    55936    // 128
#define OFF_WRED  56064    // 8*128    = 1024
#define OFF_INT   57088    // ints start here
#define SMEM_FLOATS 57088
#define SMEM_INTS   160    // items 16 + nbr 128 + count 16
#define SMEM_BYTES  (SMEM_FLOATS*4 + SMEM_INTS*4)   // 228992 B

__device__ float g_com_partial[NO];

__device__ __forceinline__ float lrelu(float v){ return v >= 0.f ? v : 0.01f*v; }
__device__ __forceinline__ float4 lrelu4(float4 v){
    return make_float4(lrelu(v.x), lrelu(v.y), lrelu(v.z), lrelu(v.w));
}
__device__ __forceinline__ void fma4(float4& a, float s, float4 w){
    a.x += s*w.x; a.y += s*w.y; a.z += s*w.z; a.w += s*w.w;
}

__device__ __forceinline__ void load_f4(float* dst, const float* src, int n){
    for (int i = threadIdx.x*4; i < n; i += 256*4)
        *(float4*)(dst+i) = *(const float4*)(src+i);
}
__device__ __forceinline__ void load_f(float* dst, const float* src, int n){
    for (int i = threadIdx.x; i < n; i += 256) dst[i] = src[i];
}

__global__ __launch_bounds__(256, 1)
void mfgn_kernel(
    const int*   __restrict__ outfit_items,
    const float* __restrict__ items_feature,
    const int*   __restrict__ items_neighbor,
    const float* __restrict__ cf_W1,  const float* __restrict__ cf_b1,
    const float* __restrict__ cf_W2,  const float* __restrict__ cf_b2,
    const float* __restrict__ f2f_W1, const float* __restrict__ f2f_b1,
    const float* __restrict__ f2f_W2, const float* __restrict__ f2f_b2,
    const float* __restrict__ f2i_W1, const float* __restrict__ f2i_b1,
    const float* __restrict__ f2i_W2, const float* __restrict__ f2i_b2,
    const float* __restrict__ i2i_W1, const float* __restrict__ i2i_b1,
    const float* __restrict__ i2i_W2, const float* __restrict__ i2i_b2,
    const float* __restrict__ o2s_W,  const float* __restrict__ o2s_b,
    float* __restrict__ d_out)
{
    extern __shared__ float sm[];
    float* s_fac  = sm + OFF_FAC;   // [item][f][d]
    float* s_feat = sm + OFF_FEAT;  // [item][d]
    float* s_W1   = sm + OFF_W1;
    float* s_W2   = sm + OFF_W2;
    float* s_h    = sm + OFF_H;
    float* s_add  = sm + OFF_ADD;
    float* s_b1   = sm + OFF_B1;
    float* s_b2   = sm + OFF_B2;
    float* s_wred = sm + OFF_WRED;
    int*   s_items = (int*)(sm + OFF_INT);
    int*   s_nbr   = s_items + NI;
    int*   s_count = s_nbr + NI*NN;

    const int o    = blockIdx.x;
    const int tid  = threadIdx.x;
    const int w    = tid >> 5;
    const int lane = tid & 31;

    if (tid < NI)    s_items[tid] = outfit_items[o*NI + tid];
    if (tid < NI*NN) s_nbr[tid]   = items_neighbor[o*NI*NN + tid];
    load_f(s_feat, items_feature + (size_t)o*NI*ND, NI*ND);
    __syncthreads();
    if (tid < NI){
        int c = 0;
        #pragma unroll
        for (int s = 0; s < NI; s++) c += (s_items[s] == tid);
        s_count[tid] = c;
    }

    // =============== Phase 1: creat_factors ===============
    for (int f = 0; f < NF; f++){
        __syncthreads();
        load_f4(s_W1, cf_W1 + f*ND*ND2, ND*ND2);
        load_f4(s_W2, cf_W2 + f*ND2*ND, ND2*ND);
        load_f(s_b1, cf_b1 + f*ND2, ND2);
        load_f(s_b2, cf_b2 + f*ND, ND);
        __syncthreads();
        // warp handles items w and w+8
        float2 b1v = *(float2*)&s_b1[lane*2];
        float2 a0 = b1v, a1 = b1v;
        #pragma unroll 4
        for (int k = 0; k < ND; k++){
            float2 wv = *(const float2*)&s_W1[k*ND2 + lane*2];
            float x0 = s_feat[w*ND + k];
            float x1 = s_feat[(w+8)*ND + k];
            a0.x += x0*wv.x; a0.y += x0*wv.y;
            a1.x += x1*wv.x; a1.y += x1*wv.y;
        }
        s_h[(w*2+0)*ND + lane*2 + 0] = lrelu(a0.x);
        s_h[(w*2+0)*ND + lane*2 + 1] = lrelu(a0.y);
        s_h[(w*2+1)*ND + lane*2 + 0] = lrelu(a1.x);
        s_h[(w*2+1)*ND + lane*2 + 1] = lrelu(a1.y);
        __syncwarp();
        float4 b2v = *(float4*)&s_b2[lane*4];
        float4 c0 = b2v, c1 = b2v;
        #pragma unroll 4
        for (int k = 0; k < ND2; k++){
            float4 wv = *(const float4*)&s_W2[k*ND + lane*4];
            float h0 = s_h[(w*2+0)*ND + k];
            float h1 = s_h[(w*2+1)*ND + k];
            fma4(c0, h0, wv);
            fma4(c1, h1, wv);
        }
        *(float4*)&s_fac[(w*NF + f)*ND + lane*4]     = lrelu4(c0);
        *(float4*)&s_fac[((w+8)*NF + f)*ND + lane*4] = lrelu4(c1);
    }

    // =============== Phase 2: inter_factors (sequential scan) ===============
    __syncthreads();
    load_f4(s_W1, f2f_W1, ND*ND);
    load_f4(s_W2, f2f_W2, ND*ND);
    load_f(s_b1, f2f_b1, ND);
    load_f(s_b2, f2f_b2, ND);
    __syncthreads();
    {
        const int f2 = w & 3;     // factor handled by this warp
        const int ch = w >> 2;    // candidate half (0: cands 0-11, 1: cands 12-23)
        for (int step = 0; step < NI; step++){
            const int i = s_items[step];
            if (i < 0) continue;   // uniform across block (shared value)

            int   offr[12];
            float mskr[12];
            #pragma unroll
            for (int r = 0; r < 12; r++){
                int idx = ch*12 + r;
                int c = (idx < NI) ? s_items[idx] : s_nbr[i*NN + (idx - NI)];
                mskr[r] = (c != -1 && c != i) ? 1.f : 0.f;
                int cc = c < 0 ? 0 : c;
                offr[r] = (cc*NF + f2)*ND;
            }
            const float* tp = s_fac + (i*NF + f2)*ND;
            float4 b1v = *(float4*)&s_b1[lane*4];
            float4 acc[12];
            #pragma unroll
            for (int r = 0; r < 12; r++) acc[r] = b1v;
            #pragma unroll 2
            for (int k = 0; k < ND; k++){
                float4 wv = *(const float4*)&s_W1[k*ND + lane*4];
                float tk = tp[k];
                float4 tw = make_float4(tk*wv.x, tk*wv.y, tk*wv.z, tk*wv.w);
                #pragma unroll
                for (int r = 0; r < 12; r++){
                    float xv = s_fac[offr[r] + k];
                    fma4(acc[r], xv, tw);
                }
            }
            #pragma unroll
            for (int r = 0; r < 12; r++)
                *(float4*)&s_h[(w*12 + r)*ND + lane*4] = lrelu4(acc[r]);
            __syncwarp();

            float4 b2v = *(float4*)&s_b2[lane*4];
            float4 acc2[12];
            #pragma unroll
            for (int r = 0; r < 12; r++) acc2[r] = b2v;
            #pragma unroll 2
            for (int k = 0; k < ND; k++){
                float4 wv = *(const float4*)&s_W2[k*ND + lane*4];
                #pragma unroll
                for (int r = 0; r < 12; r++){
                    float hv = s_h[(w*12 + r)*ND + k];
                    fma4(acc2[r], hv, wv);
                }
            }
            float4 ssum = make_float4(0.f,0.f,0.f,0.f);
            #pragma unroll
            for (int r = 0; r < 12; r++){
                float4 y = lrelu4(acc2[r]);
                fma4(ssum, mskr[r], y);
            }
            // deterministic two-stage combine across the two warps sharing f2
            if (w < 4) *(float4*)&s_add[f2*ND + lane*4] = ssum;
            __syncthreads();
            if (w >= 4){
                float4 p = *(float4*)&s_add[f2*ND + lane*4];
                p.x += ssum.x; p.y += ssum.y; p.z += ssum.z; p.w += ssum.w;
                *(float4*)&s_add[f2*ND + lane*4] = p;
            }
            __syncthreads();
            for (int idx = tid; idx < NF*ND; idx += 256)
                s_fac[i*NF*ND + idx] += s_add[idx];
            __syncthreads();
        }
    }

    // =============== com loss partial (uses final fac, positional mask) ===============
    {
        float csum = 0.f;
        #pragma unroll
        for (int t2 = 0; t2 < 2; t2++){
            int pos = w + t2*8;
            if (s_items[pos] != -1){
                const float* fp = s_fac + pos*NF*ND;
                #pragma unroll
                for (int a = 0; a < NF; a++)
                    #pragma unroll
                    for (int b = 0; b < NF; b++){
                        float p = 0.f;
                        #pragma unroll
                        for (int k = 0; k < 4; k++)
                            p += fp[a*ND + lane + 32*k] * fp[b*ND + lane + 32*k];
                        #pragma unroll
                        for (int off2 = 16; off2; off2 >>= 1)
                            p += __shfl_xor_sync(0xffffffffu, p, off2);
                        float gg = p - (a == b ? 1.f : 0.f);
                        csum += gg*gg;
                    }
            }
        }
        if (lane == 0) s_add[w] = csum;
        __syncthreads();
        if (tid == 0){
            float tot = 0.f;
            #pragma unroll
            for (int ww = 0; ww < 8; ww++) tot += s_add[ww];
            g_com_partial[o] = tot;
        }
    }

    // =============== Phase 3: infer_items ===============
    __syncthreads();
    load_f4(s_W1, f2i_W1, ND*ND);
    load_f4(s_W2, f2i_W2, ND*ND);
    load_f(s_b1, f2i_b1, ND);
    load_f(s_b2, f2i_b2, ND);
    __syncthreads();
    {
        float4 b1v = *(float4*)&s_b1[lane*4];
        float4 a[8];
        #pragma unroll
        for (int r = 0; r < 8; r++) a[r] = b1v;
        #pragma unroll 2
        for (int k = 0; k < ND; k++){
            float4 wv = *(const float4*)&s_W1[k*ND + lane*4];
            #pragma unroll
            for (int it2 = 0; it2 < 2; it2++){
                int item = w + it2*8;
                #pragma unroll
                for (int f = 0; f < NF; f++){
                    float xv = s_fac[(item*NF + f)*ND + k];
                    fma4(a[it2*4 + f], xv, wv);
                }
            }
        }
        #pragma unroll
        for (int r = 0; r < 8; r++)
            *(float4*)&s_h[(w*8 + r)*ND + lane*4] = lrelu4(a[r]);
        __syncwarp();
        float4 b2v = *(float4*)&s_b2[lane*4];
        float4 a2[8];
        #pragma unroll
        for (int r = 0; r < 8; r++) a2[r] = b2v;
        #pragma unroll 2
        for (int k = 0; k < ND; k++){
            float4 wv = *(const float4*)&s_W2[k*ND + lane*4];
            #pragma unroll
            for (int r = 0; r < 8; r++){
                float hv = s_h[(w*8 + r)*ND + k];
                fma4(a2[r], hv, wv);
            }
        }
        #pragma unroll
        for (int it2 = 0; it2 < 2; it2++){
            int item = w + it2*8;
            float4 gs = make_float4(0.f,0.f,0.f,0.f);
            #pragma unroll
            for (int f = 0; f < NF; f++){
                float4 y = lrelu4(a2[it2*4 + f]);
                gs.x += y.x; gs.y += y.y; gs.z += y.z; gs.w += y.w;
            }
            float cnt = (float)s_count[item];
            float4 fv = *(float4*)&s_feat[item*ND + lane*4];
            fma4(fv, cnt, gs);
            *(float4*)&s_feat[item*ND + lane*4] = fv;
        }
    }

    // =============== Phase 4: inter_items (sequential scan) ===============
    __syncthreads();
    load_f4(s_W1, i2i_W1, ND*ND);
    load_f4(s_W2, i2i_W2, ND*ND);
    load_f(s_b1, i2i_b1, ND);
    load_f(s_b2, i2i_b2, ND);
    __syncthreads();
    for (int step = 0; step < NI; step++){
        const int i = s_items[step];
        if (i < 0) continue;
        int   jc[2];
        float mk[2];
        #pragma unroll
        for (int r = 0; r < 2; r++){
            int sv = s_items[w + r*8];
            mk[r] = (sv != -1 && sv != i) ? 1.f : 0.f;
            jc[r] = sv < 0 ? 0 : sv;
        }
        float4 b1v = *(float4*)&s_b1[lane*4];
        float4 a0 = b1v, a1 = b1v;
        #pragma unroll 4
        for (int k = 0; k < ND; k++){
            float4 wv = *(const float4*)&s_W1[k*ND + lane*4];
            float x0 = s_feat[jc[0]*ND + k];
            float x1 = s_feat[jc[1]*ND + k];
            fma4(a0, x0, wv);
            fma4(a1, x1, wv);
        }
        *(float4*)&s_h[(w*2+0)*ND + lane*4] = lrelu4(a0);
        *(float4*)&s_h[(w*2+1)*ND + lane*4] = lrelu4(a1);
        __syncwarp();
        float4 b2v = *(float4*)&s_b2[lane*4];
        float4 c0 = b2v, c1 = b2v;
        #pragma unroll 4
        for (int k = 0; k < ND; k++){
            float4 wv = *(const float4*)&s_W2[k*ND + lane*4];
            float h0 = s_h[(w*2+0)*ND + k];
            float h1 = s_h[(w*2+1)*ND + k];
            fma4(c0, h0, wv);
            fma4(c1, h1, wv);
        }
        float4 y0 = lrelu4(c0), y1 = lrelu4(c1);
        float4 ms = make_float4(mk[0]*y0.x + mk[1]*y1.x,
                                mk[0]*y0.y + mk[1]*y1.y,
                                mk[0]*y0.z + mk[1]*y1.z,
                                mk[0]*y0.w + mk[1]*y1.w);
        *(float4*)&s_wred[w*ND + lane*4] = ms;
        __syncthreads();
        if (tid < ND){
            float s = 0.f;
            #pragma unroll
            for (int ww = 0; ww < 8; ww++) s += s_wred[ww*ND + tid];
            s_feat[i*ND + tid] += s;
        }
        __syncthreads();
    }

    // =============== Phase 5: score ===============
    if (w == 0){
        float4 ov = make_float4(0.f,0.f,0.f,0.f);
        #pragma unroll
        for (int s = 0; s < NI; s++){
            int it = s_items[s];
            if (it >= 0){
                float4 fv = *(float4*)&s_feat[it*ND + lane*4];
                ov.x += fv.x; ov.y += fv.y; ov.z += fv.z; ov.w += fv.w;
            }
        }
        float4 wv = *(const float4*)&o2s_W[lane*4];
        float p = ov.x*wv.x + ov.y*wv.y + ov.z*wv.z + ov.w*wv.w;
        #pragma unroll
        for (int off2 = 16; off2; off2 >>= 1)
            p += __shfl_xor_sync(0xffffffffu, p, off2);
        if (lane == 0) d_out[o] = 1.f / (1.f + expf(-(p + o2s_b[0])));
    }
}

__global__ void com_reduce_kernel(float* __restrict__ d_out){
    __shared__ float sb[256];
    int tid = threadIdx.x;
    float s = 0.f;
    for (int i = tid; i < NO; i += 256) s += g_com_partial[i];
    sb[tid] = s;
    __syncthreads();
    for (int st = 128; st > 0; st >>= 1){
        if (tid < st) sb[tid] += sb[tid + st];
        __syncthreads();
    }
    if (tid == 0) d_out[NO] = sb[0] / (float)NO;
}

extern "C" void kernel_launch(void* const* d_in, const int* in_sizes, int n_in,
                              void* d_out, int out_size)
{
    (void)in_sizes; (void)n_in; (void)out_size;
    cudaFuncSetAttribute(mfgn_kernel, cudaFuncAttributeMaxDynamicSharedMemorySize, SMEM_BYTES);

    const int*   outfit_items   = (const int*)  d_in[0];
    const float* items_feature  = (const float*)d_in[1];
    const int*   items_neighbor = (const int*)  d_in[2];
    // d_in[3] = items_factors (unused: reference overwrites it entirely)
    const float* cf_W1  = (const float*)d_in[4];
    const float* cf_b1  = (const float*)d_in[5];
    const float* cf_W2  = (const float*)d_in[6];
    const float* cf_b2  = (const float*)d_in[7];
    const float* f2f_W1 = (const float*)d_in[8];
    const float* f2f_b1 = (const float*)d_in[9];
    const float* f2f_W2 = (const float*)d_in[10];
    const float* f2f_b2 = (const float*)d_in[11];
    const float* f2i_W1 = (const float*)d_in[12];
    const float* f2i_b1 = (const float*)d_in[13];
    const float* f2i_W2 = (const float*)d_in[14];
    const float* f2i_b2 = (const float*)d_in[15];
    const float* i2i_W1 = (const float*)d_in[16];
    const float* i2i_b1 = (const float*)d_in[17];
    const float* i2i_W2 = (const float*)d_in[18];
    const float* i2i_b2 = (const float*)d_in[19];
    const float* o2s_W  = (const float*)d_in[20];
    const float* o2s_b  = (const float*)d_in[21];

    mfgn_kernel<<<NO, 256, SMEM_BYTES>>>(
        outfit_items, items_feature, items_neighbor,
        cf_W1, cf_b1, cf_W2, cf_b2,
        f2f_W1, f2f_b1, f2f_W2, f2f_b2,
        f2i_W1, f2i_b1, f2i_W2, f2i_b2,
        i2i_W1, i2i_b1, i2i_W2, i2i_b2,
        o2s_W, o2s_b, (float*)d_out);

    com_reduce_kernel<<<1, 256>>>((float*)d_out);
}

// round 2
// speedup vs baseline: 1.0262x; 1.0262x over previous
#include <cuda_runtime.h>
#include <math.h>

#define NO 2048
#define NI 16
#define NF 4
#define ND 128
#define NN 8
#define ND2 64

typedef unsigned long long u64;

// SMEM layout (float offsets)
#define OFF_FAC   0        // 16*4*128 = 8192
#define OFF_FEAT  8192     // 16*128   = 2048
#define OFF_W1    10240    // 16384 floats = 8192 u64
#define OFF_W2    26624    // 16384 floats = 8192 u64
#define OFF_H     43008    // 12288 floats (h: first 8192, wred: last 4096)
#define OFF_ADD   55296    // 512
#define OFF_B1    55808    // 128
#define OFF_B2    55936    // 128
#define OFF_INT   56064
#define SMEM_FLOATS 56064
#define SMEM_INTS   208    // items16 + nbr128 + count16 + cand24 + cmask24(as float bits)
#define SMEM_BYTES  (SMEM_FLOATS*4 + SMEM_INTS*4)

__device__ float g_com_partial[NO];

__device__ __forceinline__ float lrelu(float v){ return v >= 0.f ? v : 0.01f*v; }

__device__ __forceinline__ u64 packff(float lo, float hi){
    u64 d; asm("mov.b64 %0, {%1, %2};" : "=l"(d) : "f"(lo), "f"(hi)); return d;
}
__device__ __forceinline__ u64 f2fma(u64 a, u64 b, u64 c){
    u64 d; asm("fma.rn.f32x2 %0, %1, %2, %3;" : "=l"(d) : "l"(a), "l"(b), "l"(c)); return d;
}
__device__ __forceinline__ u64 f2mul(u64 a, u64 b){
    u64 d; asm("mul.rn.f32x2 %0, %1, %2;" : "=l"(d) : "l"(a), "l"(b)); return d;
}
__device__ __forceinline__ float f2red(u64 v){
    float lo, hi; asm("mov.b64 {%0, %1}, %2;" : "=f"(lo), "=f"(hi) : "l"(v));
    return lo + hi;
}

__device__ __forceinline__ void load_f(float* dst, const float* src, int n){
    for (int i = threadIdx.x; i < n; i += 256) dst[i] = src[i];
}
// Pack weight [2K rows][cols] row-major -> dst[k2*cols + d] = {W[2k2][d], W[2k2+1][d]}
__device__ __forceinline__ void load_packed(u64* dst, const float* src, int n, int cshift){
    const int cmask = (1 << cshift) - 1;
    for (int idx = threadIdx.x; idx < n; idx += 256){
        int k2 = idx >> cshift, d = idx & cmask;
        dst[idx] = packff(src[((2*k2) << cshift) + d], src[((2*k2+1) << cshift) + d]);
    }
}

__global__ __launch_bounds__(256, 1)
void mfgn_kernel(
    const int*   __restrict__ outfit_items,
    const float* __restrict__ items_feature,
    const int*   __restrict__ items_neighbor,
    const float* __restrict__ cf_W1,  const float* __restrict__ cf_b1,
    const float* __restrict__ cf_W2,  const float* __restrict__ cf_b2,
    const float* __restrict__ f2f_W1, const float* __restrict__ f2f_b1,
    const float* __restrict__ f2f_W2, const float* __restrict__ f2f_b2,
    const float* __restrict__ f2i_W1, const float* __restrict__ f2i_b1,
    const float* __restrict__ f2i_W2, const float* __restrict__ f2i_b2,
    const float* __restrict__ i2i_W1, const float* __restrict__ i2i_b1,
    const float* __restrict__ i2i_W2, const float* __restrict__ i2i_b2,
    const float* __restrict__ o2s_W,  const float* __restrict__ o2s_b,
    float* __restrict__ d_out)
{
    extern __shared__ float sm[];
    float* s_fac  = sm + OFF_FAC;   // [item][f][d]
    float* s_feat = sm + OFF_FEAT;  // [item][d]
    u64*   s_W1p  = (u64*)(sm + OFF_W1);
    u64*   s_W2p  = (u64*)(sm + OFF_W2);
    float* s_h    = sm + OFF_H;
    float* s_wred = sm + OFF_H + 8192;   // 4096 floats
    float* s_add  = sm + OFF_ADD;
    float* s_b1   = sm + OFF_B1;
    float* s_b2   = sm + OFF_B2;
    int*   s_items = (int*)(sm + OFF_INT);
    int*   s_nbr   = s_items + NI;
    int*   s_count = s_nbr + NI*NN;
    int*   s_cand  = s_count + NI;
    float* s_cmask = (float*)(s_cand + 24);

    const int o    = blockIdx.x;
    const int tid  = threadIdx.x;
    const int w    = tid >> 5;
    const int lane = tid & 31;

    if (tid < NI)    s_items[tid] = outfit_items[o*NI + tid];
    if (tid < NI*NN) s_nbr[tid]   = items_neighbor[o*NI*NN + tid];
    load_f(s_feat, items_feature + (size_t)o*NI*ND, NI*ND);
    __syncthreads();
    if (tid < NI){
        int c = 0;
        #pragma unroll
        for (int s = 0; s < NI; s++) c += (s_items[s] == tid);
        s_count[tid] = c;
    }

    // =============== Phase 1: creat_factors ===============
    for (int f = 0; f < NF; f++){
        __syncthreads();
        load_packed(s_W1p, cf_W1 + f*ND*ND2, (ND/2)*ND2, 6);   // [64 k2][64 d]
        load_packed(s_W2p, cf_W2 + f*ND2*ND, (ND2/2)*ND, 7);   // [32 k2][128 d]
        load_f(s_b1, cf_b1 + f*ND2, ND2);
        load_f(s_b2, cf_b2 + f*ND, ND);
        __syncthreads();
        // layer 1: items w, w+8; thread outputs d = lane*2, lane*2+1
        {
            u64 a00=0, a01=0, a10=0, a11=0;
            #pragma unroll 4
            for (int k2 = 0; k2 < ND/2; k2++){
                u64 x0 = *(const u64*)&s_feat[w*ND + 2*k2];
                u64 x1 = *(const u64*)&s_feat[(w+8)*ND + 2*k2];
                ulonglong2 wv = *(const ulonglong2*)&s_W1p[k2*ND2 + lane*2];
                a00 = f2fma(x0, wv.x, a00); a01 = f2fma(x0, wv.y, a01);
                a10 = f2fma(x1, wv.x, a10); a11 = f2fma(x1, wv.y, a11);
            }
            float b0 = s_b1[lane*2], b1v = s_b1[lane*2+1];
            s_h[(w*2+0)*ND2 + lane*2+0] = lrelu(f2red(a00) + b0);
            s_h[(w*2+0)*ND2 + lane*2+1] = lrelu(f2red(a01) + b1v);
            s_h[(w*2+1)*ND2 + lane*2+0] = lrelu(f2red(a10) + b0);
            s_h[(w*2+1)*ND2 + lane*2+1] = lrelu(f2red(a11) + b1v);
        }
        __syncwarp();
        // layer 2: thread outputs d = lane*4..+3
        {
            u64 c0[4] = {0,0,0,0}, c1[4] = {0,0,0,0};
            #pragma unroll 4
            for (int k2 = 0; k2 < ND2/2; k2++){
                u64 h0 = *(const u64*)&s_h[(w*2+0)*ND2 + 2*k2];
                u64 h1 = *(const u64*)&s_h[(w*2+1)*ND2 + 2*k2];
                ulonglong2 wa = *(const ulonglong2*)&s_W2p[k2*ND + lane*4];
                ulonglong2 wb = *(const ulonglong2*)&s_W2p[k2*ND + lane*4 + 2];
                c0[0]=f2fma(h0,wa.x,c0[0]); c0[1]=f2fma(h0,wa.y,c0[1]);
                c0[2]=f2fma(h0,wb.x,c0[2]); c0[3]=f2fma(h0,wb.y,c0[3]);
                c1[0]=f2fma(h1,wa.x,c1[0]); c1[1]=f2fma(h1,wa.y,c1[1]);
                c1[2]=f2fma(h1,wb.x,c1[2]); c1[3]=f2fma(h1,wb.y,c1[3]);
            }
            #pragma unroll
            for (int j = 0; j < 4; j++){
                float b = s_b2[lane*4+j];
                s_fac[(w*NF + f)*ND + lane*4 + j]     = lrelu(f2red(c0[j]) + b);
                s_fac[((w+8)*NF + f)*ND + lane*4 + j] = lrelu(f2red(c1[j]) + b);
            }
        }
    }

    // =============== Phase 2: inter_factors (sequential, compacted cands) ===============
    __syncthreads();
    load_packed(s_W1p, f2f_W1, (ND/2)*ND, 7);
    load_packed(s_W2p, f2f_W2, (ND/2)*ND, 7);
    load_f(s_b1, f2f_b1, ND);
    load_f(s_b2, f2f_b2, ND);
    __syncthreads();
    for (int step = 0; step < NI; step++){
        const int i = s_items[step];
        if (i < 0) continue;   // uniform

        // warp 0: compact valid candidates (<=15) into 16 padded slots
        if (w == 0){
            int c = 0; bool v = false;
            if (lane < NI + NN){
                c = (lane < NI) ? s_items[lane] : s_nbr[i*NN + (lane - NI)];
                v = (c != -1) && (c != i);
            }
            unsigned bal = __ballot_sync(0xffffffffu, v);
            int cnt = __popc(bal);
            if (lane < 16 && lane >= cnt){ s_cand[lane] = 0; s_cmask[lane] = 0.f; }
            if (v){
                int pos = __popc(bal & ((1u << lane) - 1));
                s_cand[pos] = c;
                s_cmask[pos] = 1.f;
            }
        }
        __syncthreads();

        const int cc0 = s_cand[w*2], cc1 = s_cand[w*2+1];
        const float m0 = s_cmask[w*2], m1 = s_cmask[w*2+1];
        const float* xb0 = s_fac + cc0*NF*ND;
        const float* xb1 = s_fac + cc1*NF*ND;
        const float* tb  = s_fac + i*NF*ND;

        // layer 1: rows r = c*4+f (8 rows), thread d = lane*4..+3
        u64 acc[8][4];
        #pragma unroll
        for (int r = 0; r < 8; r++)
            #pragma unroll
            for (int j = 0; j < 4; j++) acc[r][j] = 0;
        #pragma unroll 2
        for (int k2 = 0; k2 < ND/2; k2++){
            ulonglong2 wa = *(const ulonglong2*)&s_W1p[k2*ND + lane*4];
            ulonglong2 wb = *(const ulonglong2*)&s_W1p[k2*ND + lane*4 + 2];
            #pragma unroll
            for (int f = 0; f < NF; f++){
                u64 t = *(const u64*)&tb[f*ND + 2*k2];
                u64 x0 = *(const u64*)&xb0[f*ND + 2*k2];
                u64 x1 = *(const u64*)&xb1[f*ND + 2*k2];
                u64 tx0 = f2mul(t, x0);
                u64 tx1 = f2mul(t, x1);
                acc[f][0]   = f2fma(tx0, wa.x, acc[f][0]);
                acc[f][1]   = f2fma(tx0, wa.y, acc[f][1]);
                acc[f][2]   = f2fma(tx0, wb.x, acc[f][2]);
                acc[f][3]   = f2fma(tx0, wb.y, acc[f][3]);
                acc[4+f][0] = f2fma(tx1, wa.x, acc[4+f][0]);
                acc[4+f][1] = f2fma(tx1, wa.y, acc[4+f][1]);
                acc[4+f][2] = f2fma(tx1, wb.x, acc[4+f][2]);
                acc[4+f][3] = f2fma(tx1, wb.y, acc[4+f][3]);
            }
        }
        #pragma unroll
        for (int r = 0; r < 8; r++){
            #pragma unroll
            for (int j = 0; j < 4; j++)
                s_h[(w*8+r)*ND + lane*4 + j] = lrelu(f2red(acc[r][j]) + s_b1[lane*4+j]);
        }
        __syncwarp();

        // layer 2
        u64 acc2[8][4];
        #pragma unroll
        for (int r = 0; r < 8; r++)
            #pragma unroll
            for (int j = 0; j < 4; j++) acc2[r][j] = 0;
        #pragma unroll 2
        for (int k2 = 0; k2 < ND/2; k2++){
            ulonglong2 wa = *(const ulonglong2*)&s_W2p[k2*ND + lane*4];
            ulonglong2 wb = *(const ulonglong2*)&s_W2p[k2*ND + lane*4 + 2];
            #pragma unroll
            for (int r = 0; r < 8; r++){
                u64 h = *(const u64*)&s_h[(w*8+r)*ND + 2*k2];
                acc2[r][0] = f2fma(h, wa.x, acc2[r][0]);
                acc2[r][1] = f2fma(h, wa.y, acc2[r][1]);
                acc2[r][2] = f2fma(h, wb.x, acc2[r][2]);
                acc2[r][3] = f2fma(h, wb.y, acc2[r][3]);
            }
        }
        // masked partial sums per factor -> s_wred[w][f][d]
        #pragma unroll
        for (int f = 0; f < NF; f++){
            #pragma unroll
            for (int j = 0; j < 4; j++){
                float b = s_b2[lane*4+j];
                float y0 = lrelu(f2red(acc2[f][j])   + b);
                float y1 = lrelu(f2red(acc2[4+f][j]) + b);
                s_wred[w*512 + f*ND + lane*4 + j] = m0*y0 + m1*y1;
            }
        }
        __syncthreads();
        for (int idx = tid; idx < NF*ND; idx += 256){
            float s = 0.f;
            #pragma unroll
            for (int ww = 0; ww < 8; ww++) s += s_wred[ww*512 + idx];
            s_fac[i*NF*ND + idx] += s;
        }
        __syncthreads();
    }

    // =============== com loss partial (final fac, positional mask) ===============
    {
        float csum = 0.f;
        #pragma unroll
        for (int t2 = 0; t2 < 2; t2++){
            int pos = w + t2*8;
            if (s_items[pos] != -1){
                const float* fp = s_fac + pos*NF*ND;
                #pragma unroll
                for (int a = 0; a < NF; a++)
                    #pragma unroll
                    for (int b = 0; b < NF; b++){
                        float p = 0.f;
                        #pragma unroll
                        for (int k = 0; k < 4; k++)
                            p += fp[a*ND + lane + 32*k] * fp[b*ND + lane + 32*k];
                        #pragma unroll
                        for (int off2 = 16; off2; off2 >>= 1)
                            p += __shfl_xor_sync(0xffffffffu, p, off2);
                        float gg = p - (a == b ? 1.f : 0.f);
                        csum += gg*gg;
                    }
            }
        }
        if (lane == 0) s_add[w] = csum;
        __syncthreads();
        if (tid == 0){
            float tot = 0.f;
            #pragma unroll
            for (int ww = 0; ww < 8; ww++) tot += s_add[ww];
            g_com_partial[o] = tot;
        }
    }

    // =============== Phase 3: infer_items ===============
    __syncthreads();
    load_packed(s_W1p, f2i_W1, (ND/2)*ND, 7);
    load_packed(s_W2p, f2i_W2, (ND/2)*ND, 7);
    load_f(s_b1, f2i_b1, ND);
    load_f(s_b2, f2i_b2, ND);
    __syncthreads();
    {
        const int i0 = w*2, i1 = w*2+1;
        u64 acc[8][4];
        #pragma unroll
        for (int r = 0; r < 8; r++)
            #pragma unroll
            for (int j = 0; j < 4; j++) acc[r][j] = 0;
        #pragma unroll 2
        for (int k2 = 0; k2 < ND/2; k2++){
            ulonglong2 wa = *(const ulonglong2*)&s_W1p[k2*ND + lane*4];
            ulonglong2 wb = *(const ulonglong2*)&s_W1p[k2*ND + lane*4 + 2];
            #pragma unroll
            for (int f = 0; f < NF; f++){
                u64 x0 = *(const u64*)&s_fac[(i0*NF+f)*ND + 2*k2];
                u64 x1 = *(const u64*)&s_fac[(i1*NF+f)*ND + 2*k2];
                acc[f][0]   = f2fma(x0, wa.x, acc[f][0]);
                acc[f][1]   = f2fma(x0, wa.y, acc[f][1]);
                acc[f][2]   = f2fma(x0, wb.x, acc[f][2]);
                acc[f][3]   = f2fma(x0, wb.y, acc[f][3]);
                acc[4+f][0] = f2fma(x1, wa.x, acc[4+f][0]);
                acc[4+f][1] = f2fma(x1, wa.y, acc[4+f][1]);
                acc[4+f][2] = f2fma(x1, wb.x, acc[4+f][2]);
                acc[4+f][3] = f2fma(x1, wb.y, acc[4+f][3]);
            }
        }
        #pragma unroll
        for (int r = 0; r < 8; r++)
            #pragma unroll
            for (int j = 0; j < 4; j++)
                s_h[(w*8+r)*ND + lane*4 + j] = lrelu(f2red(acc[r][j]) + s_b1[lane*4+j]);
        __syncwarp();
        u64 acc2[8][4];
        #pragma unroll
        for (int r = 0; r < 8; r++)
            #pragma unroll
            for (int j = 0; j < 4; j++) acc2[r][j] = 0;
        #pragma unroll 2
        for (int k2 = 0; k2 < ND/2; k2++){
            ulonglong2 wa = *(const ulonglong2*)&s_W2p[k2*ND + lane*4];
            ulonglong2 wb = *(const ulonglong2*)&s_W2p[k2*ND + lane*4 + 2];
            #pragma unroll
            for (int r = 0; r < 8; r++){
                u64 h = *(const u64*)&s_h[(w*8+r)*ND + 2*k2];
                acc2[r][0] = f2fma(h, wa.x, acc2[r][0]);
                acc2[r][1] = f2fma(h, wa.y, acc2[r][1]);
                acc2[r][2] = f2fma(h, wb.x, acc2[r][2]);
                acc2[r][3] = f2fma(h, wb.y, acc2[r][3]);
            }
        }
        #pragma unroll
        for (int c = 0; c < 2; c++){
            int item = (c == 0) ? i0 : i1;
            float cnt = (float)s_count[item];
            #pragma unroll
            for (int j = 0; j < 4; j++){
                float b = s_b2[lane*4+j];
                float gs = 0.f;
                #pragma unroll
                for (int f = 0; f < NF; f++)
                    gs += lrelu(f2red(acc2[c*4+f][j]) + b);
                s_feat[item*ND + lane*4 + j] += cnt * gs;
            }
        }
    }

    // =============== Phase 4: inter_items (sequential) ===============
    __syncthreads();
    load_packed(s_W1p, i2i_W1, (ND/2)*ND, 7);
    load_packed(s_W2p, i2i_W2, (ND/2)*ND, 7);
    load_f(s_b1, i2i_b1, ND);
    load_f(s_b2, i2i_b2, ND);
    __syncthreads();
    for (int step = 0; step < NI; step++){
        const int i = s_items[step];
        if (i < 0) continue;
        int   jc[2];
        float mk[2];
        #pragma unroll
        for (int r = 0; r < 2; r++){
            int sv = s_items[w + r*8];
            mk[r] = (sv != -1 && sv != i) ? 1.f : 0.f;
            jc[r] = sv < 0 ? 0 : sv;
        }
        u64 a0[4] = {0,0,0,0}, a1[4] = {0,0,0,0};
        #pragma unroll 4
        for (int k2 = 0; k2 < ND/2; k2++){
            u64 x0 = *(const u64*)&s_feat[jc[0]*ND + 2*k2];
            u64 x1 = *(const u64*)&s_feat[jc[1]*ND + 2*k2];
            ulonglong2 wa = *(const ulonglong2*)&s_W1p[k2*ND + lane*4];
            ulonglong2 wb = *(const ulonglong2*)&s_W1p[k2*ND + lane*4 + 2];
            a0[0]=f2fma(x0,wa.x,a0[0]); a0[1]=f2fma(x0,wa.y,a0[1]);
            a0[2]=f2fma(x0,wb.x,a0[2]); a0[3]=f2fma(x0,wb.y,a0[3]);
            a1[0]=f2fma(x1,wa.x,a1[0]); a1[1]=f2fma(x1,wa.y,a1[1]);
            a1[2]=f2fma(x1,wb.x,a1[2]); a1[3]=f2fma(x1,wb.y,a1[3]);
        }
        #pragma unroll
        for (int j = 0; j < 4; j++){
            float b = s_b1[lane*4+j];
            s_h[(w*2+0)*ND + lane*4 + j] = lrelu(f2red(a0[j]) + b);
            s_h[(w*2+1)*ND + lane*4 + j] = lrelu(f2red(a1[j]) + b);
        }
        __syncwarp();
        u64 c0[4] = {0,0,0,0}, c1[4] = {0,0,0,0};
        #pragma unroll 4
        for (int k2 = 0; k2 < ND/2; k2++){
            u64 h0 = *(const u64*)&s_h[(w*2+0)*ND + 2*k2];
            u64 h1 = *(const u64*)&s_h[(w*2+1)*ND + 2*k2];
            ulonglong2 wa = *(const ulonglong2*)&s_W2p[k2*ND + lane*4];
            ulonglong2 wb = *(const ulonglong2*)&s_W2p[k2*ND + lane*4 + 2];
            c0[0]=f2fma(h0,wa.x,c0[0]); c0[1]=f2fma(h0,wa.y,c0[1]);
            c0[2]=f2fma(h0,wb.x,c0[2]); c0[3]=f2fma(h0,wb.y,c0[3]);
            c1[0]=f2fma(h1,wa.x,c1[0]); c1[1]=f2fma(h1,wa.y,c1[1]);
            c1[2]=f2fma(h1,wb.x,c1[2]); c1[3]=f2fma(h1,wb.y,c1[3]);
        }
        #pragma unroll
        for (int j = 0; j < 4; j++){
            float b = s_b2[lane*4+j];
            float y0 = lrelu(f2red(c0[j]) + b);
            float y1 = lrelu(f2red(c1[j]) + b);
            s_wred[w*ND + lane*4 + j] = mk[0]*y0 + mk[1]*y1;
        }
        __syncthreads();
        if (tid < ND){
            float s = 0.f;
            #pragma unroll
            for (int ww = 0; ww < 8; ww++) s += s_wred[ww*ND + tid];
            s_feat[i*ND + tid] += s;
        }
        __syncthreads();
    }

    // =============== Phase 5: score ===============
    if (w == 0){
        float4 ov = make_float4(0.f,0.f,0.f,0.f);
        #pragma unroll
        for (int s = 0; s < NI; s++){
            int it = s_items[s];
            if (it >= 0){
                float4 fv = *(float4*)&s_feat[it*ND + lane*4];
                ov.x += fv.x; ov.y += fv.y; ov.z += fv.z; ov.w += fv.w;
            }
        }
        const float4 wv = *(const float4*)&o2s_W[lane*4];
        float p = ov.x*wv.x + ov.y*wv.y + ov.z*wv.z + ov.w*wv.w;
        #pragma unroll
        for (int off2 = 16; off2; off2 >>= 1)
            p += __shfl_xor_sync(0xffffffffu, p, off2);
        if (lane == 0) d_out[o] = 1.f / (1.f + expf(-(p + o2s_b[0])));
    }
}

__global__ void com_reduce_kernel(float* __restrict__ d_out){
    __shared__ float sb[256];
    int tid = threadIdx.x;
    float s = 0.f;
    for (int i = tid; i < NO; i += 256) s += g_com_partial[i];
    sb[tid] = s;
    __syncthreads();
    for (int st = 128; st > 0; st >>= 1){
        if (tid < st) sb[tid] += sb[tid + st];
        __syncthreads();
    }
    if (tid == 0) d_out[NO] = sb[0] / (float)NO;
}

extern "C" void kernel_launch(void* const* d_in, const int* in_sizes, int n_in,
                              void* d_out, int out_size)
{
    (void)in_sizes; (void)n_in; (void)out_size;
    cudaFuncSetAttribute(mfgn_kernel, cudaFuncAttributeMaxDynamicSharedMemorySize, SMEM_BYTES);

    const int*   outfit_items   = (const int*)  d_in[0];
    const float* items_feature  = (const float*)d_in[1];
    const int*   items_neighbor = (const int*)  d_in[2];
    const float* cf_W1  = (const float*)d_in[4];
    const float* cf_b1  = (const float*)d_in[5];
    const float* cf_W2  = (const float*)d_in[6];
    const float* cf_b2  = (const float*)d_in[7];
    const float* f2f_W1 = (const float*)d_in[8];
    const float* f2f_b1 = (const float*)d_in[9];
    const float* f2f_W2 = (const float*)d_in[10];
    const float* f2f_b2 = (const float*)d_in[11];
    const float* f2i_W1 = (const float*)d_in[12];
    const float* f2i_b1 = (const float*)d_in[13];
    const float* f2i_W2 = (const float*)d_in[14];
    const float* f2i_b2 = (const float*)d_in[15];
    const float* i2i_W1 = (const float*)d_in[16];
    const float* i2i_b1 = (const float*)d_in[17];
    const float* i2i_W2 = (const float*)d_in[18];
    const float* i2i_b2 = (const float*)d_in[19];
    const float* o2s_W  = (const float*)d_in[20];
    const float* o2s_b  = (const float*)d_in[21];

    mfgn_kernel<<<NO, 256, SMEM_BYTES>>>(
        outfit_items, items_feature, items_neighbor,
        cf_W1, cf_b1, cf_W2, cf_b2,
        f2f_W1, f2f_b1, f2f_W2, f2f_b2,
        f2i_W1, f2i_b1, f2i_W2, f2i_b2,
        i2i_W1, i2i_b1, i2i_W2, i2i_b2,
        o2s_W, o2s_b, (float*)d_out);

    com_reduce_kernel<<<1, 256>>>((float*)d_out);
}